// round 5
// baseline (speedup 1.0000x reference)
#include <cuda_runtime.h>
#include <cstdint>

#define EPS 1e-5f
#define NBATCH 16
#define PER (4 * 1024 * 1024)             // elements per batch
#define PER4 (PER / 4)                    // float4s per batch = 1,048,576

#define THREADS 512
#define BLOCKS_PER_SM 3
#define NBLK (148 * BLOCKS_PER_SM)        // 444 — co-resident even on 148-SM floor

#define ITEM_F4 8192                      // 512 thr * 16 float4 = 128KB per item
#define ITEMS_PER_BATCH (PER4 / ITEM_F4)  // 128
#define NITEMS (NBATCH * ITEMS_PER_BATCH) // 2048
#define F4_PER_THREAD 16

// Scratch (allocation-free -> __device__ globals, zero-initialized)
__device__ float        g_psum[NITEMS];
__device__ float        g_psumsq[NITEMS];
__device__ unsigned int g_pcnt[NITEMS];
__device__ float        g_mean[NBATCH];
__device__ float        g_inv[NBATCH];
__device__ unsigned int g_bar;            // monotonic grid-barrier counter (never reset)

// Monotonic-counter grid barrier: replay-safe, no reset required.
// Each instance consumes NBLK increments; target = next multiple of NBLK.
__device__ __forceinline__ void grid_barrier() {
    __syncthreads();
    if (threadIdx.x == 0) {
        __threadfence();                              // release my writes
        unsigned int old = atomicAdd(&g_bar, 1u);
        unsigned int target = (old / NBLK + 1u) * NBLK;
        long long spins = 0;
        while (atomicAdd(&g_bar, 0u) < target) {
            __nanosleep(64);
            if (++spins > 200000000LL) break;         // bail instead of hang
        }
    }
    __syncthreads();
    __threadfence();                                  // acquire others' writes
}

__global__ __launch_bounds__(THREADS, BLOCKS_PER_SM)
void fused_masked_normalize(const float4* __restrict__ x, float4* __restrict__ out) {
    const int t    = threadIdx.x;
    const int lane = t & 31;
    const int warp = t >> 5;

    __shared__ float        sh_s[THREADS / 32];
    __shared__ float        sh_ss[THREADS / 32];
    __shared__ unsigned int sh_c[THREADS / 32];

    // ---------------- Phase 1: per-item (sum, sumsq, nnz) partials ----------
    // Masked entries are exactly 0.0f, so sum/sumsq over ALL elements equal
    // the masked sums -> branch-free loads/FMAs; only count needs compares.
    for (int item = blockIdx.x; item < NITEMS; item += NBLK) {
        const size_t base = (size_t)(item >> 7) * PER4
                          + (size_t)(item & (ITEMS_PER_BATCH - 1)) * ITEM_F4 + t;

        float s = 0.f, ss = 0.f;
        unsigned int c = 0;

        #pragma unroll
        for (int half = 0; half < 2; half++) {
            float4 v[8];
            #pragma unroll
            for (int k = 0; k < 8; k++)
                v[k] = x[base + (size_t)(half * 8 + k) * THREADS];
            #pragma unroll
            for (int k = 0; k < 8; k++) {
                s  += v[k].x + v[k].y + v[k].z + v[k].w;
                ss  = fmaf(v[k].x, v[k].x, ss);
                ss  = fmaf(v[k].y, v[k].y, ss);
                ss  = fmaf(v[k].z, v[k].z, ss);
                ss  = fmaf(v[k].w, v[k].w, ss);
                c  += (v[k].x != 0.f) + (v[k].y != 0.f) + (v[k].z != 0.f) + (v[k].w != 0.f);
            }
        }

        // block reduce (deterministic)
        #pragma unroll
        for (int off = 16; off > 0; off >>= 1) {
            s  += __shfl_xor_sync(0xFFFFFFFFu, s,  off);
            ss += __shfl_xor_sync(0xFFFFFFFFu, ss, off);
            c  += __shfl_xor_sync(0xFFFFFFFFu, c,  off);
        }
        if (lane == 0) { sh_s[warp] = s; sh_ss[warp] = ss; sh_c[warp] = c; }
        __syncthreads();
        if (warp == 0) {
            s  = (lane < THREADS / 32) ? sh_s[lane]  : 0.f;
            ss = (lane < THREADS / 32) ? sh_ss[lane] : 0.f;
            c  = (lane < THREADS / 32) ? sh_c[lane]  : 0u;
            #pragma unroll
            for (int off = 8; off > 0; off >>= 1) {
                s  += __shfl_xor_sync(0xFFFFFFFFu, s,  off);
                ss += __shfl_xor_sync(0xFFFFFFFFu, ss, off);
                c  += __shfl_xor_sync(0xFFFFFFFFu, c,  off);
            }
            if (lane == 0) { g_psum[item] = s; g_psumsq[item] = ss; g_pcnt[item] = c; }
        }
        __syncthreads();
    }

    grid_barrier();

    // ---------------- Finalize: blocks 0..15, one batch each ----------------
    if (blockIdx.x < NBATCH) {
        const int b = blockIdx.x;
        double ds = 0.0, dss = 0.0;
        unsigned long long dc = 0;
        if (t < ITEMS_PER_BATCH) {
            const int idx = b * ITEMS_PER_BATCH + t;
            ds  = (double)g_psum[idx];
            dss = (double)g_psumsq[idx];
            dc  = g_pcnt[idx];
        }
        #pragma unroll
        for (int off = 16; off > 0; off >>= 1) {
            ds  += __shfl_xor_sync(0xFFFFFFFFu, ds,  off);
            dss += __shfl_xor_sync(0xFFFFFFFFu, dss, off);
            dc  += __shfl_xor_sync(0xFFFFFFFFu, dc,  off);
        }
        __shared__ double fs[THREADS / 32];
        __shared__ double fss[THREADS / 32];
        __shared__ unsigned long long fc[THREADS / 32];
        if (lane == 0) { fs[warp] = ds; fss[warp] = dss; fc[warp] = dc; }
        __syncthreads();
        if (t == 0) {
            double S = 0.0, SS = 0.0; unsigned long long C = 0;
            #pragma unroll
            for (int w = 0; w < (ITEMS_PER_BATCH + 31) / 32; w++) { S += fs[w]; SS += fss[w]; C += fc[w]; }
            const double n    = (double)C;
            const double mean = S / n;
            const double var  = (SS - S * S / n) / (n - 1.0);   // m2 term analytically 0
            g_mean[b] = (float)mean;
            g_inv[b]  = (float)(1.0 / (sqrt(var) + (double)EPS));
        }
    }

    grid_barrier();

    // ---------------- Phase 2: normalize --------------------------------
    for (int item = blockIdx.x; item < NITEMS; item += NBLK) {
        const int b = item >> 7;
        const size_t base = (size_t)b * PER4
                          + (size_t)(item & (ITEMS_PER_BATCH - 1)) * ITEM_F4 + t;
        const float mean = g_mean[b];
        const float inv  = g_inv[b];

        #pragma unroll
        for (int half = 0; half < 2; half++) {
            float4 v[8];
            #pragma unroll
            for (int k = 0; k < 8; k++)
                v[k] = x[base + (size_t)(half * 8 + k) * THREADS];
            #pragma unroll
            for (int k = 0; k < 8; k++) {
                float4 o;
                o.x = (v[k].x != 0.f) ? (v[k].x - mean) * inv : 0.f;
                o.y = (v[k].y != 0.f) ? (v[k].y - mean) * inv : 0.f;
                o.z = (v[k].z != 0.f) ? (v[k].z - mean) * inv : 0.f;
                o.w = (v[k].w != 0.f) ? (v[k].w - mean) * inv : 0.f;
                out[base + (size_t)(half * 8 + k) * THREADS] = o;
            }
        }
    }
}

extern "C" void kernel_launch(void* const* d_in, const int* in_sizes, int n_in,
                              void* d_out, int out_size) {
    const float4* x   = (const float4*)d_in[0];
    float4*       out = (float4*)d_out;
    fused_masked_normalize<<<NBLK, THREADS>>>(x, out);
}